// round 16
// baseline (speedup 1.0000x reference)
#include <cuda_runtime.h>
#include <cuda_bf16.h>
#include <cstdint>

// Problem constants (fixed by the dataset):
//   x: [B=4096, D=2048], weight: [C=32768, D=2048], weight2: [D, D]
//   out: [B, C] float32
#define DDIM 2048
#define BMAX 4096
#define CMAX 32768
#define EPS_NRM 1e-12f

// Scratch (allocation-free rule: __device__ globals). Every element is
// overwritten (or reset) every launch -> deterministic across graph replays.
__device__ float g_part[4][DDIM];  // partial column sum-of-squares of weight2
__device__ float g_s[DDIM];        // s[d] = sum_j weight2[d,j] * inv_cn[j]
__device__ float g_xs[BMAX];       // xn . s
__device__ int   g_xs_done;        // producer/consumer counter (reset by k_rowsum_fin)

// ---------------------------------------------------------------------------
// 1) Partial column sum-of-squares of weight2. grid (64, 4): 256 blocks so all
//    SMs pull on the 16 MB read. Leaves w2 L2-resident for kernel 2.
// ---------------------------------------------------------------------------
__global__ void k_colnorm_part(const float* __restrict__ w2) {
    int j = blockIdx.x * 32 + threadIdx.x;
    int d0 = blockIdx.y * (DDIM / 4);
    float acc = 0.0f;
    #pragma unroll 8
    for (int d = threadIdx.y; d < DDIM / 4; d += 16) {
        float v = __ldg(&w2[(size_t)(d0 + d) * DDIM + j]);
        acc = fmaf(v, v, acc);
    }
    __shared__ float sh[16][32];
    sh[threadIdx.y][threadIdx.x] = acc;
    __syncthreads();
    if (threadIdx.y == 0) {
        float t = 0.0f;
        #pragma unroll
        for (int y = 0; y < 16; y++) t += sh[y][threadIdx.x];
        g_part[blockIdx.y][j] = t;
    }
}

// ---------------------------------------------------------------------------
// 2) Fused finalize + row-sums: each block rebuilds inv_cn into SMEM from the
//    4 partials (L2-hot), then 8 warps do warp-per-row dot(w2_row, inv_cn).
//    w2 is L2-resident after kernel 1 -> fast. Also resets g_xs_done.
// ---------------------------------------------------------------------------
__global__ void k_rowsum_fin(const float* __restrict__ w2) {
    __shared__ float4 s_icn[DDIM / 4];   // 8 KB
    {
        float* icn = reinterpret_cast<float*>(s_icn);
        for (int j = threadIdx.x; j < DDIM; j += 256) {
            float t = g_part[0][j] + g_part[1][j] + g_part[2][j] + g_part[3][j];
            icn[j] = 1.0f / fmaxf(sqrtf(t), EPS_NRM);
        }
    }
    if (blockIdx.x == 0 && threadIdx.x == 0) g_xs_done = 0;  // reset handoff
    __syncthreads();

    int warp = threadIdx.x >> 5;
    int lane = threadIdx.x & 31;
    int d = blockIdx.x * 8 + warp;
    const float4* row = reinterpret_cast<const float4*>(w2 + (size_t)d * DDIM);
    float dot = 0.0f;
    #pragma unroll
    for (int i = 0; i < 2; i++) {
        float4 a[8];
        #pragma unroll
        for (int k = 0; k < 8; k++)
            a[k] = __ldg(&row[lane + (i * 8 + k) * 32]);
        #pragma unroll
        for (int k = 0; k < 8; k++) {
            float4 c = s_icn[lane + (i * 8 + k) * 32];
            dot += a[k].x * c.x + a[k].y * c.y + a[k].z * c.z + a[k].w * c.w;
        }
    }
    #pragma unroll
    for (int o = 16; o; o >>= 1) dot += __shfl_xor_sync(0xffffffffu, dot, o);
    if (lane == 0) g_s[d] = dot;
}

// ---------------------------------------------------------------------------
// Shared body: warp computes dot(row, s_sh) and ||row||^2, 16 float4/lane in
// two bursts of 8 outstanding LDG.128. Returns normalized dot in lane 0.
// ---------------------------------------------------------------------------
__device__ __forceinline__ float warp_norm_dot(const float4* __restrict__ row,
                                               const float4* __restrict__ s_sh,
                                               int lane) {
    float dot = 0.0f, ss = 0.0f;
    #pragma unroll
    for (int i = 0; i < 2; i++) {
        float4 a[8];
        #pragma unroll
        for (int k = 0; k < 8; k++)
            a[k] = __ldcs(&row[lane + (i * 8 + k) * 32]);
        #pragma unroll
        for (int k = 0; k < 8; k++) {
            float4 s4 = s_sh[lane + (i * 8 + k) * 32];
            dot += a[k].x * s4.x + a[k].y * s4.y + a[k].z * s4.z + a[k].w * s4.w;
            ss  += a[k].x * a[k].x + a[k].y * a[k].y + a[k].z * a[k].z + a[k].w * a[k].w;
        }
    }
    #pragma unroll
    for (int o = 16; o; o >>= 1) {
        dot += __shfl_xor_sync(0xffffffffu, dot, o);
        ss  += __shfl_xor_sync(0xffffffffu, ss, o);
    }
    return dot / fmaxf(sqrtf(ss), EPS_NRM);
}

// ---------------------------------------------------------------------------
// 3) Mega kernel.
//    blocks [0, B/64):        xs producer — 8 warps x 8 rows of x -> g_xs,
//                             then fence + counter bump.
//    blocks [B/64, B/64+C/64): own 64 classes. Phase 1: compute 64 ms values
//                             into SMEM (the 256 MB weight read). Then wait on
//                             the counter (free: xs finishes far earlier),
//                             stage xs (L2, __ldcg), and stream the 1 MB
//                             output tile with __stcs.
// ---------------------------------------------------------------------------
#define XS_BLOCKS (BMAX / 64)   // 64
__global__ void __launch_bounds__(256)
k_mega(const float* __restrict__ xmat, const float* __restrict__ wmat,
       float* __restrict__ out, int B, int C) {
    __shared__ float4 s_sh[DDIM / 4];   // 8 KB: s vector
    __shared__ float  s_ms[64];         // this block's 64 ms values
    __shared__ float  s_xs[BMAX];       // 16 KB: all xs (consumer blocks)

    int tid  = threadIdx.x;
    int warp = tid >> 5;
    int lane = tid & 31;

    // stage s once per block
    {
        const float4* sv = reinterpret_cast<const float4*>(g_s);
        #pragma unroll
        for (int i = tid; i < DDIM / 4; i += 256) s_sh[i] = sv[i];
    }
    __syncthreads();

    if (blockIdx.x < XS_BLOCKS) {
        // ---- xs producer ----
        int r0 = blockIdx.x * 64 + warp * 8;
        #pragma unroll
        for (int rr = 0; rr < 8; rr++) {
            int r = r0 + rr;
            const float4* row = reinterpret_cast<const float4*>(xmat + (size_t)r * DDIM);
            float v = warp_norm_dot(row, s_sh, lane);
            if (lane == 0) g_xs[r] = v;
        }
        __threadfence();
        __syncthreads();
        if (tid == 0) atomicAdd(&g_xs_done, 1);
        return;
    }

    // ---- ms + logit consumer ----
    int c0 = (blockIdx.x - XS_BLOCKS) * 64;

    // Phase 1: 64 ms values (8 warps x 8 rows)
    #pragma unroll
    for (int rr = 0; rr < 8; rr++) {
        int r = c0 + warp * 8 + rr;
        const float4* row = reinterpret_cast<const float4*>(wmat + (size_t)r * DDIM);
        float v = warp_norm_dot(row, s_sh, lane);
        if (lane == 0) s_ms[warp * 8 + rr] = v;
    }

    // Wait for xs (already done by now: phase 1 chip time >> xs time)
    if (tid == 0) {
        while (*(volatile int*)&g_xs_done != XS_BLOCKS) __nanosleep(64);
    }
    __syncthreads();

    // Stage all xs from L2 (bypass L1 for freshness)
    for (int i = tid; i < B; i += 256) s_xs[i] = __ldcg(&g_xs[i]);
    __syncthreads();

    // Phase 2: stream out[b, c0:c0+64] for all b. thread -> (b%16, c4 in 0..15)
    int c4   = tid & 15;          // float4 index within 64-c chunk
    int brow = tid >> 4;          // 16 b-rows per iteration
    float4 m = make_float4(s_ms[c4 * 4 + 0], s_ms[c4 * 4 + 1],
                           s_ms[c4 * 4 + 2], s_ms[c4 * 4 + 3]);
    size_t rowq = (size_t)(C >> 2);
    float4* o4 = reinterpret_cast<float4*>(out) + (c0 >> 2) + c4;

    #pragma unroll 4
    for (int b = brow; b < B; b += 16) {
        float xsb = s_xs[b];
        float4 r = make_float4(m.x - xsb, m.y - xsb, m.z - xsb, m.w - xsb);
        __stcs(&o4[(size_t)b * rowq], r);
    }
}

// ---------------------------------------------------------------------------
extern "C" void kernel_launch(void* const* d_in, const int* in_sizes, int n_in,
                              void* d_out, int out_size) {
    const float* x  = (const float*)d_in[0];   // [B, D]
    const float* w  = (const float*)d_in[1];   // [C, D]
    const float* w2 = (const float*)d_in[2];   // [D, D]
    float* out = (float*)d_out;                // [B, C]

    const int B = in_sizes[0] / DDIM;          // 4096
    const int C = in_sizes[1] / DDIM;          // 32768

    // 1) partial column norms of weight2
    k_colnorm_part<<<dim3(DDIM / 32, 4), dim3(32, 16)>>>(w2);
    // 2) finalize inv_cn (in SMEM) + s row-sums, reset handoff counter
    k_rowsum_fin<<<DDIM / 8, 256>>>(w2);
    // 3) xs producer blocks + fused ms/logit consumer blocks
    k_mega<<<B / 64 + C / 64, 256>>>(x, w, out, B, C);
}

// round 17
// speedup vs baseline: 1.1590x; 1.1590x over previous
#include <cuda_runtime.h>
#include <cuda_bf16.h>
#include <cstdint>

// Problem constants (fixed by the dataset):
//   x: [B=4096, D=2048], weight: [C=32768, D=2048], weight2: [D, D]
//   out: [B, C] float32
#define DDIM 2048
#define BMAX 4096
#define CMAX 32768
#define EPS_NRM 1e-12f

// Scratch (allocation-free rule: __device__ globals). Every element is
// overwritten every launch -> deterministic across graph replays.
__device__ float g_part[16][DDIM]; // partial column sum-of-squares of weight2
__device__ float g_s[DDIM];        // s[d] = sum_j weight2[d,j] * inv_cn[j]
__device__ float g_xs[BMAX];       // xn . s
__device__ float g_ms[CMAX];       // mean . s

// ---------------------------------------------------------------------------
// 1) Partial column sum-of-squares of weight2, float4 all the way.
//    grid (16 col-chunks, 16 row-chunks) = 256 blocks; block (32, 8).
//    Each thread: 16 independent LDG.128 down its column chunk (MLP=16).
// ---------------------------------------------------------------------------
__global__ void k_colnorm_part(const float* __restrict__ w2) {
    int j4 = blockIdx.x * 32 + threadIdx.x;      // float4 column index
    int d0 = blockIdx.y * 128;                    // row chunk base
    const float4* w4 = reinterpret_cast<const float4*>(w2);

    float4 acc = make_float4(0.f, 0.f, 0.f, 0.f);
    #pragma unroll 16
    for (int d = threadIdx.y; d < 128; d += 8) {
        float4 v = __ldg(&w4[(size_t)(d0 + d) * (DDIM / 4) + j4]);
        acc.x = fmaf(v.x, v.x, acc.x);
        acc.y = fmaf(v.y, v.y, acc.y);
        acc.z = fmaf(v.z, v.z, acc.z);
        acc.w = fmaf(v.w, v.w, acc.w);
    }
    __shared__ float4 sh[8][32];
    sh[threadIdx.y][threadIdx.x] = acc;
    __syncthreads();
    if (threadIdx.y == 0) {
        float4 t = sh[0][threadIdx.x];
        #pragma unroll
        for (int y = 1; y < 8; y++) {
            float4 u = sh[y][threadIdx.x];
            t.x += u.x; t.y += u.y; t.z += u.z; t.w += u.w;
        }
        reinterpret_cast<float4*>(g_part[blockIdx.y])[j4] = t;
    }
}

// ---------------------------------------------------------------------------
// 2) Fused finalize + row-sums: each block rebuilds inv_cn into SMEM from the
//    16 partials (L2-hot), then 8 warps do warp-per-row dot(w2_row, inv_cn).
//    w2 is L2-resident after kernel 1 (16 MB << 126 MB L2).
// ---------------------------------------------------------------------------
__global__ void k_rowsum_fin(const float* __restrict__ w2) {
    __shared__ float4 s_icn[DDIM / 4];   // 8 KB
    {
        float* icn = reinterpret_cast<float*>(s_icn);
        for (int j = threadIdx.x; j < DDIM; j += 256) {
            float t = 0.0f;
            #pragma unroll
            for (int p = 0; p < 16; p++) t += g_part[p][j];
            icn[j] = 1.0f / fmaxf(sqrtf(t), EPS_NRM);
        }
    }
    __syncthreads();

    int warp = threadIdx.x >> 5;
    int lane = threadIdx.x & 31;
    int d = blockIdx.x * 8 + warp;
    const float4* row = reinterpret_cast<const float4*>(w2 + (size_t)d * DDIM);
    float dot = 0.0f;
    #pragma unroll
    for (int i = 0; i < 2; i++) {
        float4 a[8];
        #pragma unroll
        for (int k = 0; k < 8; k++)
            a[k] = __ldg(&row[lane + (i * 8 + k) * 32]);
        #pragma unroll
        for (int k = 0; k < 8; k++) {
            float4 c = s_icn[lane + (i * 8 + k) * 32];
            dot += a[k].x * c.x + a[k].y * c.y + a[k].z * c.z + a[k].w * c.w;
        }
    }
    #pragma unroll
    for (int o = 16; o; o >>= 1) dot += __shfl_xor_sync(0xffffffffu, dot, o);
    if (lane == 0) g_s[d] = dot;
}

// ---------------------------------------------------------------------------
// 3) Fused xs/ms: one WARP per row, bursts of 8 outstanding LDG.128 per lane,
//    s staged once per block in SMEM, shuffle-only reduction.
//    First B warps do x -> g_xs, the rest do weight -> g_ms.
// ---------------------------------------------------------------------------
__global__ void k_norm_dot_fused(const float* __restrict__ xmat,
                                 const float* __restrict__ wmat,
                                 int B) {
    __shared__ float4 s_sh[DDIM / 4];   // 8 KB
    {
        const float4* sv = reinterpret_cast<const float4*>(g_s);
        #pragma unroll
        for (int i = threadIdx.x; i < DDIM / 4; i += 256) s_sh[i] = sv[i];
    }
    __syncthreads();

    int warp = threadIdx.x >> 5;
    int lane = threadIdx.x & 31;
    int gr = blockIdx.x * 8 + warp;      // global row id over B + C rows

    const float* mat;
    float* outp;
    int r;
    if (gr < B) { mat = xmat; outp = g_xs; r = gr; }
    else        { mat = wmat; outp = g_ms; r = gr - B; }

    const float4* row = reinterpret_cast<const float4*>(mat + (size_t)r * DDIM);
    float dot = 0.0f, ss = 0.0f;

    #pragma unroll
    for (int i = 0; i < 2; i++) {
        float4 a[8];
        #pragma unroll
        for (int k = 0; k < 8; k++)
            a[k] = __ldcs(&row[lane + (i * 8 + k) * 32]);
        #pragma unroll
        for (int k = 0; k < 8; k++) {
            float4 s4 = s_sh[lane + (i * 8 + k) * 32];
            dot += a[k].x * s4.x + a[k].y * s4.y + a[k].z * s4.z + a[k].w * s4.w;
            ss  += a[k].x * a[k].x + a[k].y * a[k].y + a[k].z * a[k].z + a[k].w * a[k].w;
        }
    }

    #pragma unroll
    for (int o = 16; o; o >>= 1) {
        dot += __shfl_xor_sync(0xffffffffu, dot, o);
        ss  += __shfl_xor_sync(0xffffffffu, ss, o);
    }
    if (lane == 0)
        outp[r] = dot / fmaxf(sqrtf(ss), EPS_NRM);
}

// ---------------------------------------------------------------------------
// 4) out[b,c] = ms[c] - xs[b]. b-tiled: each block owns a [16 b x 2048 c]
//    tile, reads its ms chunk ONCE into registers, stages 16 xs in SMEM,
//    streams row-contiguous 8 KB chunks with __stcs (no L2 churn).
// ---------------------------------------------------------------------------
#define TILE_B 16
__global__ void k_logit(float* __restrict__ out, int Cdim) {
    __shared__ float s_xs[TILE_B];
    if (threadIdx.x < TILE_B)
        s_xs[threadIdx.x] = g_xs[blockIdx.y * TILE_B + threadIdx.x];
    __syncthreads();

    const float4* ms4 = reinterpret_cast<const float4*>(g_ms);
    int c4_0 = blockIdx.x * 512 + threadIdx.x;        // 2048 c = 512 float4
    int c4_1 = c4_0 + 256;
    float4 m0 = __ldg(&ms4[c4_0]);
    float4 m1 = __ldg(&ms4[c4_1]);

    size_t rowq = (size_t)(Cdim >> 2);
    float4* o4 = reinterpret_cast<float4*>(out) +
                 (size_t)blockIdx.y * TILE_B * rowq;

    #pragma unroll
    for (int bb = 0; bb < TILE_B; bb++) {
        float xsb = s_xs[bb];
        float4 r0 = make_float4(m0.x - xsb, m0.y - xsb, m0.z - xsb, m0.w - xsb);
        float4 r1 = make_float4(m1.x - xsb, m1.y - xsb, m1.z - xsb, m1.w - xsb);
        __stcs(&o4[bb * rowq + c4_0], r0);
        __stcs(&o4[bb * rowq + c4_1], r1);
    }
}

// ---------------------------------------------------------------------------
extern "C" void kernel_launch(void* const* d_in, const int* in_sizes, int n_in,
                              void* d_out, int out_size) {
    const float* x  = (const float*)d_in[0];   // [B, D]
    const float* w  = (const float*)d_in[1];   // [C, D]
    const float* w2 = (const float*)d_in[2];   // [D, D]
    float* out = (float*)d_out;                // [B, C]

    const int B = in_sizes[0] / DDIM;          // 4096
    const int C = in_sizes[1] / DDIM;          // 32768

    // 1) partial column norms of weight2 (float4, 256 blocks)
    k_colnorm_part<<<dim3(16, 16), dim3(32, 8)>>>(w2);
    // 2) finalize inv_cn (SMEM) + s row-sums (w2 L2-hot)
    k_rowsum_fin<<<DDIM / 8, 256>>>(w2);
    // 3) xs[b] and ms[c] fused, warp-per-row
    k_norm_dot_fused<<<(B + C) / 8, 256>>>(x, w, B);
    // 4) logit stream-out (512 MB write), b-tiled 16x2048, row-contiguous
    dim3 grid4(C / 2048, B / TILE_B);
    k_logit<<<grid4, 256>>>(out, C);
}